// round 15
// baseline (speedup 1.0000x reference)
#include <cuda_runtime.h>

// Problem shape (fixed by the reference).
#define BB 4
#define SS 4096
#define DD 64
#define TQ 64
#define TK 64
#define LDQ 65          // smem stride for Q/K/E tiles (bank-friendly)
#define NQT (SS / TQ)   // 64 query tiles per batch

// Per-row softmax denominators (partial sums combined via atomicAdd).
__device__ float g_rowsum[BB * SS];

// ---------------------------------------------------------------------------
// Kernel Z: zero the outv accumulator and g_rowsum (both are atomic targets).
// ---------------------------------------------------------------------------
__global__ void zero_partials_kernel(float* __restrict__ outv)
{
    const int i = blockIdx.x * blockDim.x + threadIdx.x;
    if (i < BB * SS * DD) outv[i] = 0.f;
    if (i < BB * SS)      g_rowsum[i] = 0.f;
}

// ---------------------------------------------------------------------------
// Kernel A (R9 inner loop, k-split for occupancy): grid (NQT, BB, 2).
// CTA (qt, b, s) processes key tiles [klo, khi) of query tile qt:
//   s=0 -> [0, h), s=1 -> [h, qt+1), h=(qt+1)/2  (sizes differ by <=1).
// 512 CTAs, 2 resident per SM (16 warps/SM) -> cross-CTA latency hiding.
// Per key tile kb: sync; store prefetched K/V regs -> smem; LDG prefetch kb+1;
// sync; QK GEMM; exp+mask; E -> own smem buffer (half-warp private rows) +
// unnormalized weights STG; __syncwarp(); PV GEMM.
// Epilogue: partial rowsum/O combined via atomicAdd; kernel B normalizes.
// ---------------------------------------------------------------------------
__global__ __launch_bounds__(256, 2)
void attn_fused_kernel(const float* __restrict__ Q, const float* __restrict__ K,
                       const float* __restrict__ V, float* __restrict__ outv,
                       float* __restrict__ outw)
{
    extern __shared__ float sm[];
    float* Qs = sm;                      // TQ * LDQ
    float* Ks = Qs + TQ * LDQ;           // TK * LDQ
    float* Es = Ks + TK * LDQ;           // TQ * LDQ (separate from Ks)
    float* Vs = Es + TQ * LDQ;           // TK * 64

    const int b   = blockIdx.y;
    const int qt  = blockIdx.x;
    const int spl = blockIdx.z;
    const int q0  = qt * TQ;
    const int h   = (qt + 1) >> 1;
    const int klo = spl ? h : 0;
    const int khi = spl ? (qt + 1) : h;

    const int t  = threadIdx.x;
    const int ty = t >> 4;          // 0..15 -> query micro-rows 4*ty..4*ty+3
    const int tx = t & 15;          // 0..15 -> key/d micro-cols 4*tx..4*tx+3

    // Per-thread K/V copy slots: i = t + 256*s -> row i>>4, col (i&15)*4
    int cp_r[4], cp_c[4];
    #pragma unroll
    for (int s = 0; s < 4; ++s) {
        const int i = t + 256 * s;
        cp_r[s] = i >> 4;
        cp_c[s] = (i & 15) << 2;
    }

    // Load Q tile [TQ x DD] into smem (scalar stores: LDQ rows unaligned).
    #pragma unroll
    for (int s = 0; s < 4; ++s) {
        const int r = cp_r[s], c = cp_c[s];
        const float4 v4 = *(const float4*)(Q + ((size_t)b * SS + q0 + r) * DD + c);
        float* dst = Qs + r * LDQ + c;
        dst[0] = v4.x; dst[1] = v4.y; dst[2] = v4.z; dst[3] = v4.w;
    }

    float o[4][4];
    float rsum[4];
    #pragma unroll
    for (int i = 0; i < 4; ++i) {
        rsum[i] = 0.f;
        #pragma unroll
        for (int j = 0; j < 4; ++j) o[i][j] = 0.f;
    }

    // Prefetch first K/V tile of this CTA's range.
    float4 kr[4], vr[4];
    if (klo < khi) {
        #pragma unroll
        for (int s = 0; s < 4; ++s) {
            const size_t goff =
                ((size_t)b * SS + (size_t)klo * TK + cp_r[s]) * DD + cp_c[s];
            kr[s] = *(const float4*)(K + goff);
            vr[s] = *(const float4*)(V + goff);
        }
    }

    for (int kb = klo; kb < khi; ++kb) {
        __syncthreads();  // prev iteration's QK/PV reads of Ks/Vs done
                          // (also orders Q-store at kb==klo)

        // Store prefetched K/V registers into smem.
        #pragma unroll
        for (int s = 0; s < 4; ++s) {
            const int r = cp_r[s], c = cp_c[s];
            float* kd = Ks + r * LDQ + c;
            kd[0] = kr[s].x; kd[1] = kr[s].y; kd[2] = kr[s].z; kd[3] = kr[s].w;
            *(float4*)(Vs + r * 64 + c) = vr[s];
        }

        // Issue prefetch for kb+1 (latency hides under this kb's compute).
        if (kb + 1 < khi) {
            #pragma unroll
            for (int s = 0; s < 4; ++s) {
                const size_t goff =
                    ((size_t)b * SS + (size_t)(kb + 1) * TK + cp_r[s]) * DD + cp_c[s];
                kr[s] = *(const float4*)(K + goff);
                vr[s] = *(const float4*)(V + goff);
            }
        }
        __syncthreads();  // K/V tile visible to all

        // ---- S-tile = Q K^T (4x4 register micro-tile per thread) ----
        float acc[4][4];
        #pragma unroll
        for (int i = 0; i < 4; ++i)
            #pragma unroll
            for (int j = 0; j < 4; ++j) acc[i][j] = 0.f;

        const float* qp = Qs + (4 * ty) * LDQ;
        const float* kp = Ks + (4 * tx) * LDQ;
        #pragma unroll 8
        for (int kk = 0; kk < DD; ++kk) {
            const float qa0 = qp[kk];
            const float qa1 = qp[LDQ + kk];
            const float qa2 = qp[2 * LDQ + kk];
            const float qa3 = qp[3 * LDQ + kk];
            const float kv0 = kp[kk];
            const float kv1 = kp[LDQ + kk];
            const float kv2 = kp[2 * LDQ + kk];
            const float kv3 = kp[3 * LDQ + kk];
            acc[0][0] += qa0 * kv0; acc[0][1] += qa0 * kv1; acc[0][2] += qa0 * kv2; acc[0][3] += qa0 * kv3;
            acc[1][0] += qa1 * kv0; acc[1][1] += qa1 * kv1; acc[1][2] += qa1 * kv2; acc[1][3] += qa1 * kv3;
            acc[2][0] += qa2 * kv0; acc[2][1] += qa2 * kv1; acc[2][2] += qa2 * kv2; acc[2][3] += qa2 * kv3;
            acc[3][0] += qa3 * kv0; acc[3][1] += qa3 * kv1; acc[3][2] += qa3 * kv2; acc[3][3] += qa3 * kv3;
        }

        // e = exp(S/8), causal mask on diagonal tile (only split 1 sees it).
        float e[4][4];
        const bool diag = (kb == qt);
        #pragma unroll
        for (int i = 0; i < 4; ++i) {
            #pragma unroll
            for (int j = 0; j < 4; ++j) {
                float ev = __expf(acc[i][j] * 0.125f);
                if (diag && (4 * tx + j > 4 * ty + i)) ev = 0.f;  // k > q
                e[i][j] = ev;
                rsum[i] += ev;
            }
        }

        // Store E tile (own buffer) and write unnormalized weights.
        // Rows 4*ty..4*ty+3 of Es are written AND read only by the 16
        // threads sharing this ty (one half-warp) -> syncwarp suffices.
        #pragma unroll
        for (int i = 0; i < 4; ++i) {
            float* ed = Es + (4 * ty + i) * LDQ + 4 * tx;
            ed[0] = e[i][0]; ed[1] = e[i][1]; ed[2] = e[i][2]; ed[3] = e[i][3];
            *(float4*)(outw + ((size_t)b * SS + q0 + 4 * ty + i) * SS + kb * TK + 4 * tx)
                = make_float4(e[i][0], e[i][1], e[i][2], e[i][3]);
        }
        __syncwarp();

        // ---- O += E @ V (V rows as conflict-free float4) ----
        const float* ep = Es + (4 * ty) * LDQ;
        const float* vp = Vs + 4 * tx;
        #pragma unroll 8
        for (int c = 0; c < TK; ++c) {
            const float e0 = ep[c];
            const float e1 = ep[LDQ + c];
            const float e2 = ep[2 * LDQ + c];
            const float e3 = ep[3 * LDQ + c];
            const float4 vv = *(const float4*)(vp + c * 64);
            o[0][0] += e0 * vv.x; o[0][1] += e0 * vv.y; o[0][2] += e0 * vv.z; o[0][3] += e0 * vv.w;
            o[1][0] += e1 * vv.x; o[1][1] += e1 * vv.y; o[1][2] += e1 * vv.z; o[1][3] += e1 * vv.w;
            o[2][0] += e2 * vv.x; o[2][1] += e2 * vv.y; o[2][2] += e2 * vv.z; o[2][3] += e2 * vv.w;
            o[3][0] += e3 * vv.x; o[3][1] += e3 * vv.y; o[3][2] += e3 * vv.z; o[3][3] += e3 * vv.w;
        }
    }

    // Reduce partial rowsums across the 16 tx lanes, combine via atomics.
    #pragma unroll
    for (int m = 8; m >= 1; m >>= 1) {
        #pragma unroll
        for (int i = 0; i < 4; ++i)
            rsum[i] += __shfl_xor_sync(0xffffffffu, rsum[i], m);
    }
    if (tx == 0) {
        #pragma unroll
        for (int i = 0; i < 4; ++i)
            atomicAdd(&g_rowsum[b * SS + q0 + 4 * ty + i], rsum[i]);
    }

    // Accumulate partial O into outv (normalized later by kernel B).
    #pragma unroll
    for (int i = 0; i < 4; ++i) {
        float* op = outv + ((size_t)b * SS + q0 + 4 * ty + i) * DD + 4 * tx;
        #pragma unroll
        for (int j = 0; j < 4; ++j)
            atomicAdd(op + j, o[i][j]);
    }

    // Zero the masked weight columns [ (qt+1)*TK, SS ) -- split 1 owns them.
    if (spl == 1) {
        const int kend = (qt + 1) * TK;
        const int nvec = (SS - kend) >> 2;
        if (nvec > 0) {
            const float4 z = make_float4(0.f, 0.f, 0.f, 0.f);
            for (int r = 0; r < TQ; ++r) {
                float* rowp = outw + ((size_t)b * SS + q0 + r) * SS + kend;
                for (int c = t; c < nvec; c += 256)
                    *(float4*)(rowp + (c << 2)) = z;
            }
        }
    }
}

// ---------------------------------------------------------------------------
// Kernel B: per row q, scale the causal part of the weights row AND the outv
// row by 1/rowsum. Each block handles the balanced row pair (q, 4095-q).
// ---------------------------------------------------------------------------
__device__ __forceinline__ void norm_row(float* __restrict__ outw,
                                         float* __restrict__ outv, int b, int q)
{
    const float inv = 1.0f / g_rowsum[b * SS + q];
    float* row = outw + ((size_t)b * SS + q) * SS;
    const int n  = q + 1;       // causal entries in this row
    const int n4 = n >> 2;
    for (int i = threadIdx.x; i < n4; i += blockDim.x) {
        float4 w = ((float4*)row)[i];
        w.x *= inv; w.y *= inv; w.z *= inv; w.w *= inv;
        ((float4*)row)[i] = w;
    }
    for (int i = (n4 << 2) + threadIdx.x; i < n; i += blockDim.x)
        row[i] *= inv;
    if (threadIdx.x < DD / 4) {
        float4* vp = (float4*)(outv + ((size_t)b * SS + q) * DD);
        float4 w = vp[threadIdx.x];
        w.x *= inv; w.y *= inv; w.z *= inv; w.w *= inv;
        vp[threadIdx.x] = w;
    }
}

__global__ void norm_weights_kernel(float* __restrict__ outw,
                                    float* __restrict__ outv)
{
    const int b = blockIdx.y;
    norm_row(outw, outv, b, blockIdx.x);            // short row
    norm_row(outw, outv, b, SS - 1 - blockIdx.x);   // long row (pair = 4097)
}

extern "C" void kernel_launch(void* const* d_in, const int* in_sizes, int n_in,
                              void* d_out, int out_size)
{
    const float* Q = (const float*)d_in[0];
    const float* K = (const float*)d_in[1];
    const float* V = (const float*)d_in[2];
    float* outv = (float*)d_out;                      // attn_vec  [B,S,D]
    float* outw = outv + (size_t)BB * SS * DD;        // attn_weights [B,S,S]

    const size_t smem_bytes =
        (size_t)(3 * TQ * LDQ + TK * 64) * sizeof(float);  // 66,304 B

    // >48KB dynamic smem requires the opt-in attribute (idempotent, capture-safe).
    cudaFuncSetAttribute(attn_fused_kernel,
                         cudaFuncAttributeMaxDynamicSharedMemorySize, 68 * 1024);

    zero_partials_kernel<<<(BB * SS * DD + 255) / 256, 256>>>(outv);
    attn_fused_kernel<<<dim3(NQT, BB, 2), 256, smem_bytes>>>(Q, K, V, outv, outw);
    norm_weights_kernel<<<dim3(SS / 2, BB), 256>>>(outw, outv);
}